// round 8
// baseline (speedup 1.0000x reference)
#include <cuda_runtime.h>
#include <cstdint>

// Problem constants (fixed shapes)
#define T_LEN 512
#define B_SZ  256
#define C_SZ  4
#define K_SZ  64
#define L2E   1.4426950408889634f
#define LN2   0.6931471805599453f

// ---------- small PTX helpers ----------
static __device__ __forceinline__ float ex2f(float x) {
    float y; asm("ex2.approx.ftz.f32 %0, %1;" : "=f"(y) : "f"(x)); return y;
}
static __device__ __forceinline__ float lg2f(float x) {
    float y; asm("lg2.approx.f32 %0, %1;" : "=f"(y) : "f"(x)); return y;
}
static __device__ __forceinline__ unsigned long long pk2(float lo, float hi) {
    unsigned long long r;
    asm("mov.b64 %0, {%1, %2};" : "=l"(r) : "f"(lo), "f"(hi));
    return r;
}
static __device__ __forceinline__ void upk2(unsigned long long v, float& lo, float& hi) {
    asm("mov.b64 {%0, %1}, %2;" : "=f"(lo), "=f"(hi) : "l"(v));
}
// packed dual-FP32 FMA (Blackwell f32x2 pipe)
static __device__ __forceinline__ void fma2(unsigned long long& d,
                                            unsigned long long a,
                                            unsigned long long b) {
    asm("fma.rn.f32x2 %0, %1, %2, %0;" : "+l"(d) : "l"(a), "l"(b));
}
static __device__ __forceinline__ unsigned long long add2(unsigned long long a,
                                                          unsigned long long b) {
    unsigned long long d;
    asm("add.rn.f32x2 %0, %1, %2;" : "=l"(d) : "l"(a), "l"(b));
    return d;
}
// exact power-of-two renormalizer from fp32 exponent field (validated in R7)
static __device__ __forceinline__ void renorm(float v, float& r, float& ee) {
    const unsigned nb = __float_as_uint(v);
    const int ef = (int)(nb >> 23);
    ee = (float)(ef - 127);
    r  = __uint_as_float((unsigned)(254 - ef) << 23);   // 2^-(ef-127)
}

// One probability-space forward step for TWO chains (A, B) sharing one block.
// Invariant: aA == exp2(alphaA*L2E - M2A) etc. One __syncthreads serves both
// broadcasts; the two FMA/LDS streams interleave for ILP.
#define CRF_STEP2(EVA, EVB, TT, P)                                             \
    do {                                                                       \
        const float EtA = ex2f((EVA) * L2E);                                   \
        const float EtB = ex2f((EVB) * L2E);                                   \
        {   /* branch-free depth-4 prefetch (clamped re-read is harmless) */   \
            const int tn = min((TT) + 4, T_LEN - 1);                           \
            const float* pp = e0p + (size_t)tn * tstride;                      \
            (EVA) = __ldcs(pp + tid);                                          \
            (EVB) = __ldcs(pp + K_SZ + tid);                                   \
        }                                                                      \
        psh[P][0][tid] = aA;                                                   \
        psh[P][1][tid] = aB;                                                   \
        __syncthreads();                                                       \
        const ulonglong2* pdA = reinterpret_cast<const ulonglong2*>(&psh[P][0][0]); \
        const ulonglong2* pdB = reinterpret_cast<const ulonglong2*>(&psh[P][1][0]); \
        unsigned long long acA0 = 0ull, acA1 = 0ull;                           \
        unsigned long long acB0 = 0ull, acB1 = 0ull;                           \
        float normA = 1.f, normB = 1.f;                                        \
        _Pragma("unroll")                                                      \
        for (int i = 0; i < 16; i++) {                                         \
            ulonglong2 qA = pdA[i];                                            \
            ulonglong2 qB = pdB[i];                                            \
            if (i == 0) {                                                      \
                float lo, hi;                                                  \
                upk2(qA.x, lo, hi); normA = lo;                                \
                upk2(qB.x, lo, hi); normB = lo;                                \
            }                                                                  \
            fma2(acA0, qA.x, EA[2 * i]);                                       \
            fma2(acB0, qB.x, EB[2 * i]);                                       \
            fma2(acA1, qA.y, EA[2 * i + 1]);                                   \
            fma2(acB1, qB.y, EB[2 * i + 1]);                                   \
        }                                                                      \
        float rA, eeA, rB, eeB;                                                \
        renorm(normA, rA, eeA);                                                \
        renorm(normB, rB, eeB);                                                \
        {                                                                      \
            unsigned long long sA = add2(acA0, acA1);                          \
            unsigned long long sB = add2(acB0, acB1);                          \
            float al, ah, bl, bh;                                              \
            upk2(sA, al, ah);                                                  \
            upk2(sB, bl, bh);                                                  \
            aA = (al + ah) * (EtA * rA);                                       \
            aB = (bl + bh) * (EtB * rB);                                       \
        }                                                                      \
        M2A += eeA;                                                            \
        M2B += eeB;                                                            \
    } while (0)

// Two (b, c) chains per 64-thread block: chains (b, 2q) and (b, 2q+1) share
// the same token length L[b] (uniform control flow). Thread tid owns state
// kn = tid of BOTH chains.
__global__ void __launch_bounds__(64)
crf_fwd_kernel(const float* __restrict__ emis,    // (T,B,C,K)
               const int*   __restrict__ tags,    // (T,B,C)
               const int*   __restrict__ tok,     // (B,)
               const float* __restrict__ trans,   // (C,K,K)
               const float* __restrict__ startt,  // (C,K)
               const float* __restrict__ endt,    // (C,K)
               float*       __restrict__ out)     // (B,C)
{
    // Double-buffered broadcast of the two a-vectors.
    __shared__ __align__(16) float psh[2][2][K_SZ];

    const int blk = blockIdx.x;
    const int b  = blk >> 1;
    const int c0 = (blk & 1) << 1;       // chain A channel
    const int c1 = c0 + 1;               // chain B channel
    const int tid  = threadIdx.x;
    const int lane = tid & 31;
    const int wid  = tid >> 5;
    const unsigned FULL = 0xffffffffu;

    int L = tok[b];
    L = min(max(L, 1), T_LEN);

    // ============ numerator partials: warp w handles chain c0 + w ============
    const int cw = c0 + wid;
    float nacc = 0.f;
    for (int t = 1 + lane; t < L; t += 32) {
        int tp = tags[((t - 1) * B_SZ + b) * C_SZ + cw];
        int tc = tags[(t * B_SZ + b) * C_SZ + cw];
        nacc += trans[(cw * K_SZ + tp) * K_SZ + tc]
              + emis[(((size_t)t * B_SZ + b) * C_SZ + cw) * K_SZ + tc];
    }
    #pragma unroll
    for (int off = 16; off; off >>= 1)
        nacc += __shfl_xor_sync(FULL, nacc, off);
    // lane 0 of warp w now holds chain (c0+w)'s tag-path partial sum.

    // ============ F matrices: column tid of exp(trans[c0]) and exp(trans[c1])
    unsigned long long EA[32], EB[32];
    {
        const float* tr0 = trans + c0 * K_SZ * K_SZ;
        const float* tr1 = tr0 + K_SZ * K_SZ;
        #pragma unroll
        for (int j = 0; j < 32; j++) {
            EA[j] = pk2(__expf(tr0[(2 * j)     * K_SZ + tid]),
                        __expf(tr0[(2 * j + 1) * K_SZ + tid]));
            EB[j] = pk2(__expf(tr1[(2 * j)     * K_SZ + tid]),
                        __expf(tr1[(2 * j + 1) * K_SZ + tid]));
        }
    }

    // ============ init ============
    const float* e0p = emis + ((size_t)b * C_SZ + c0) * K_SZ;  // t=0, chain A
    const size_t tstride = (size_t)B_SZ * C_SZ * K_SZ;

    const float a0A = (startt[c0 * K_SZ + tid] + e0p[tid])        * L2E;
    const float a0B = (startt[c1 * K_SZ + tid] + e0p[K_SZ + tid]) * L2E;
    if (tid == 0) { psh[0][0][0] = a0A; psh[0][1][0] = a0B; }
    __syncthreads();
    const float m0A = psh[0][0][0];
    const float m0B = psh[0][1][0];
    float aA  = ex2f(a0A - m0A);
    float aB  = ex2f(a0B - m0B);
    float M2A = m0A;
    float M2B = m0B;

    // Depth-4 prefetch ring for both chains (slices 1..4 always in-bounds).
    float pA0 = __ldcs(e0p + 1 * tstride + tid);
    float pB0 = __ldcs(e0p + 1 * tstride + K_SZ + tid);
    float pA1 = __ldcs(e0p + 2 * tstride + tid);
    float pB1 = __ldcs(e0p + 2 * tstride + K_SZ + tid);
    float pA2 = __ldcs(e0p + 3 * tstride + tid);
    float pB2 = __ldcs(e0p + 3 * tstride + K_SZ + tid);
    float pA3 = __ldcs(e0p + 4 * tstride + tid);
    float pB3 = __ldcs(e0p + 4 * tstride + K_SZ + tid);

    // Main recursion, unrolled x4 (fixed prefetch slots, constant parity).
    int t = 1;
    while (t < L) {
        CRF_STEP2(pA0, pB0, t, 1); if (++t >= L) break;
        CRF_STEP2(pA1, pB1, t, 0); if (++t >= L) break;
        CRF_STEP2(pA2, pB2, t, 1); if (++t >= L) break;
        CRF_STEP2(pA3, pB3, t, 0); ++t;
    }

    // ============ denominators: logsumexp over 64 states per chain ============
    const float xA = lg2f(aA) + endt[c0 * K_SZ + tid] * L2E;
    const float xB = lg2f(aB) + endt[c1 * K_SZ + tid] * L2E;
    float mmA = xA, mmB = xB;
    #pragma unroll
    for (int off = 16; off; off >>= 1) {
        mmA = fmaxf(mmA, __shfl_xor_sync(FULL, mmA, off));
        mmB = fmaxf(mmB, __shfl_xor_sync(FULL, mmB, off));
    }
    float seA = ex2f(xA - mmA);
    float seB = ex2f(xB - mmB);
    #pragma unroll
    for (int off = 16; off; off >>= 1) {
        seA += __shfl_xor_sync(FULL, seA, off);
        seB += __shfl_xor_sync(FULL, seB, off);
    }

    __syncthreads();                       // psh free for the combine
    float* red = &psh[0][0][0];
    if (lane == 0) {
        red[wid * 8 + 0] = mmA;  red[wid * 8 + 1] = seA;
        red[wid * 8 + 2] = mmB;  red[wid * 8 + 3] = seB;
        red[wid * 8 + 4] = nacc;           // chain (c0+wid) numerator partial
    }
    __syncthreads();

    // tid 0 writes chain A; tid 32 writes chain B (has chain B's nacc context).
    if (tid == 0 || tid == 32) {
        const int isB = wid;               // 0 → chain A, 1 → chain B
        const int cc  = c0 + isB;
        const float mw0 = red[0 + 2 * isB], sw0 = red[1 + 2 * isB];
        const float mw1 = red[8 + 2 * isB], sw1 = red[9 + 2 * isB];
        const float mx  = fmaxf(mw0, mw1);
        const float st  = sw0 * ex2f(mw0 - mx) + sw1 * ex2f(mw1 - mx);
        const float M2  = isB ? M2B : M2A;
        const float den = (M2 + mx + lg2f(st)) * LN2;

        const float nsum = red[4] * 0.f + red[4 + 0] * 0.f   // (no cross mix)
                         + 0.f;                              // placeholder, see below
        (void)nsum;
        const float napart = red[isB * 8 + 4];               // own chain partial

        const int tag0 = tags[b * C_SZ + cc];
        const int tagL = tags[((L - 1) * B_SZ + b) * C_SZ + cc];
        const float num = napart
                        + startt[cc * K_SZ + tag0]
                        + e0p[isB * K_SZ + tag0]
                        + endt[cc * K_SZ + tagL];

        out[b * C_SZ + cc] = num - den;
    }
}

extern "C" void kernel_launch(void* const* d_in, const int* in_sizes, int n_in,
                              void* d_out, int out_size) {
    const float* emis   = (const float*)d_in[0];
    const int*   tags   = (const int*)  d_in[1];
    const int*   tok    = (const int*)  d_in[2];
    const float* trans  = (const float*)d_in[3];
    const float* startt = (const float*)d_in[4];
    const float* endt   = (const float*)d_in[5];
    float* out = (float*)d_out;

    crf_fwd_kernel<<<(B_SZ * C_SZ) / 2, 64>>>(emis, tags, tok, trans, startt, endt, out);
}

// round 9
// speedup vs baseline: 1.1005x; 1.1005x over previous
#include <cuda_runtime.h>
#include <cstdint>

// Problem constants (fixed shapes)
#define T_LEN 512
#define B_SZ  256
#define C_SZ  4
#define K_SZ  64
#define L2E   1.4426950408889634f
#define LN2   0.6931471805599453f

#define N_CHAIN (B_SZ * C_SZ)        // 1024

// Scratch for the forward/backward meet (allocation-free rule: device globals)
__device__ float g_vec[2 * N_CHAIN][K_SZ];   // [2*chain + dir][state]
__device__ float g_m2 [2 * N_CHAIN];         // log2 offsets
__device__ float g_num[N_CHAIN];             // finished numerators

// ---------- small PTX helpers ----------
static __device__ __forceinline__ float ex2f(float x) {
    float y; asm("ex2.approx.ftz.f32 %0, %1;" : "=f"(y) : "f"(x)); return y;
}
static __device__ __forceinline__ float lg2f(float x) {
    float y; asm("lg2.approx.f32 %0, %1;" : "=f"(y) : "f"(x)); return y;
}
static __device__ __forceinline__ unsigned long long pk2(float lo, float hi) {
    unsigned long long r;
    asm("mov.b64 %0, {%1, %2};" : "=l"(r) : "f"(lo), "f"(hi));
    return r;
}
static __device__ __forceinline__ void upk2(unsigned long long v, float& lo, float& hi) {
    asm("mov.b64 {%0, %1}, %2;" : "=f"(lo), "=f"(hi) : "l"(v));
}
// packed dual-FP32 FMA (Blackwell f32x2 pipe)
static __device__ __forceinline__ void fma2(unsigned long long& d,
                                            unsigned long long a,
                                            unsigned long long b) {
    asm("fma.rn.f32x2 %0, %1, %2, %0;" : "+l"(d) : "l"(a), "l"(b));
}
static __device__ __forceinline__ unsigned long long add2(unsigned long long a,
                                                          unsigned long long b) {
    unsigned long long d;
    asm("add.rn.f32x2 %0, %1, %2;" : "=l"(d) : "l"(a), "l"(b));
    return d;
}
// exact power-of-two renormalizer from fp32 exponent field (validated R7)
static __device__ __forceinline__ void renorm(float v, float& r, float& ee) {
    const unsigned nb = __float_as_uint(v);
    const int ef = (int)(nb >> 23);
    ee = (float)(ef - 127);
    r  = __uint_as_float((unsigned)(254 - ef) << 23);   // 2^-(ef-127)
}

// 64-wide dot product from the broadcast vector in buf against 32 packed
// F-register pairs; also extracts buf[0] (the renormalizer source).
#define MATVEC(BUF, SUMV, NORMV)                                               \
    do {                                                                       \
        const ulonglong2* pd = reinterpret_cast<const ulonglong2*>(BUF);       \
        unsigned long long ac0 = 0ull, ac1 = 0ull, ac2 = 0ull, ac3 = 0ull;     \
        _Pragma("unroll")                                                      \
        for (int i = 0; i < 16; i++) {                                         \
            ulonglong2 q = pd[i];                                              \
            if (i == 0) { float lo, hi; upk2(q.x, lo, hi); (NORMV) = lo; }     \
            fma2(ac0, q.x, E[2 * i]);                                          \
            fma2(ac1, q.y, E[2 * i + 1]);                                      \
            if (++i >= 16) break;                                              \
            q = pd[i];                                                         \
            fma2(ac2, q.x, E[2 * i]);                                          \
            fma2(ac3, q.y, E[2 * i + 1]);                                      \
        }                                                                      \
        unsigned long long s2 = add2(add2(ac0, ac1), add2(ac2, ac3));          \
        float sl, sh;                                                          \
        upk2(s2, sl, sh);                                                      \
        (SUMV) = sl + sh;                                                      \
    } while (0)

// Forward step (R7-proven): emission applied AFTER the matvec.
#define STEP_F(EV, TT, P)                                                      \
    do {                                                                       \
        const float Et = ex2f((EV) * L2E);                                     \
        {   const int tn = min((TT) + 4, T_LEN - 1);                           \
            (EV) = __ldcs(e0p + (size_t)tn * tstride + tid); }                 \
        psh[P][tid] = a;                                                       \
        __syncthreads();                                                       \
        float sum, nrm;                                                        \
        MATVEC(&psh[P][0], sum, nrm);                                          \
        float r, ee;                                                           \
        renorm(nrm, r, ee);                                                    \
        a = sum * (Et * r);                                                    \
        M2 += ee;                                                              \
    } while (0)

// Backward step: emission folded BEFORE the matvec (b' = F (E_t ∘ b)).
#define STEP_B(EV, TT, P)                                                      \
    do {                                                                       \
        const float ct = a * ex2f((EV) * L2E);                                 \
        {   const int tn = max((TT) - 4, 0);                                   \
            (EV) = __ldcs(e0p + (size_t)tn * tstride + tid); }                 \
        psh[P][tid] = ct;                                                      \
        __syncthreads();                                                       \
        float sum, nrm;                                                        \
        MATVEC(&psh[P][0], sum, nrm);                                          \
        float r, ee;                                                           \
        renorm(nrm, r, ee);                                                    \
        a = sum * r;                                                           \
        M2 += ee;                                                              \
    } while (0)

// One half-chain per 64-thread block. blk = 2*chain + dir.
//   dir 0: forward,  steps t = 1..mid,   also computes the numerator.
//   dir 1: backward, steps t = L-1..mid+1.
__global__ void __launch_bounds__(64)
crf_half_kernel(const float* __restrict__ emis,    // (T,B,C,K)
                const int*   __restrict__ tags,    // (T,B,C)
                const int*   __restrict__ tok,     // (B,)
                const float* __restrict__ trans,   // (C,K,K)
                const float* __restrict__ startt,  // (C,K)
                const float* __restrict__ endt)    // (C,K)
{
    __shared__ __align__(16) float psh[2][K_SZ];

    const int blk   = blockIdx.x;
    const int dir   = blk & 1;
    const int chain = blk >> 1;
    const int b = chain >> 2;
    const int c = chain & 3;
    const int tid  = threadIdx.x;
    const int lane = tid & 31;
    const int wid  = tid >> 5;
    const unsigned FULL = 0xffffffffu;

    int L = tok[b];
    L = min(max(L, 1), T_LEN);
    const int mid = (L - 1) >> 1;

    const float* e0p = emis + ((size_t)b * C_SZ + c) * K_SZ;   // t=0 slice
    const size_t tstride = (size_t)B_SZ * C_SZ * K_SZ;
    const float* tr = trans + c * K_SZ * K_SZ;

    // ===== numerator (forward blocks only; overlaps the F-exp prologue) =====
    float nacc = 0.f;
    if (dir == 0) {
        for (int t = 1 + tid; t < L; t += 64) {
            int tp = tags[((t - 1) * B_SZ + b) * C_SZ + c];
            int tc = tags[(t * B_SZ + b) * C_SZ + c];
            nacc += trans[(c * K_SZ + tp) * K_SZ + tc]
                  + emis[(((size_t)t * B_SZ + b) * C_SZ + c) * K_SZ + tc];
        }
    }

    // ===== F registers =====
    // forward: thread owns OUT state tid  -> column tid of F (strided rows)
    // backward: thread owns state tid     -> row tid of F (contiguous)
    unsigned long long E[32];
    if (dir == 0) {
        #pragma unroll
        for (int j = 0; j < 32; j++)
            E[j] = pk2(__expf(tr[(2 * j)     * K_SZ + tid]),
                       __expf(tr[(2 * j + 1) * K_SZ + tid]));
    } else {
        #pragma unroll
        for (int j = 0; j < 32; j++)
            E[j] = pk2(__expf(tr[tid * K_SZ + 2 * j]),
                       __expf(tr[tid * K_SZ + 2 * j + 1]));
    }

    float a, M2;

    if (dir == 0) {
        // ---- forward init at t=0 ----
        const float a0 = (startt[c * K_SZ + tid] + e0p[tid]) * L2E;
        if (tid == 0) psh[0][0] = a0;
        __syncthreads();
        const float m0 = psh[0][0];
        a  = ex2f(a0 - m0);
        M2 = m0;

        // depth-4 prefetch ring, slices 1..4 (always in-bounds)
        float p0 = __ldcs(e0p + 1 * tstride + tid);
        float p1 = __ldcs(e0p + 2 * tstride + tid);
        float p2 = __ldcs(e0p + 3 * tstride + tid);
        float p3 = __ldcs(e0p + 4 * tstride + tid);

        int t = 1;
        while (t <= mid) {
            STEP_F(p0, t, 1); if (++t > mid) break;
            STEP_F(p1, t, 0); if (++t > mid) break;
            STEP_F(p2, t, 1); if (++t > mid) break;
            STEP_F(p3, t, 0); ++t;
        }

        // finish the numerator: block-reduce nacc, add boundary terms
        #pragma unroll
        for (int off = 16; off; off >>= 1)
            nacc += __shfl_xor_sync(FULL, nacc, off);
        __syncthreads();
        if (lane == 0) psh[0][32 + wid] = nacc;   // slots unused by a-store below? no: write scratch first
        __syncthreads();
        if (tid == 0) {
            const int tag0 = tags[b * C_SZ + c];
            const int tagL = tags[((L - 1) * B_SZ + b) * C_SZ + c];
            g_num[chain] = psh[0][32] + psh[0][33]
                         + startt[c * K_SZ + tag0]
                         + e0p[tag0]
                         + endt[c * K_SZ + tagL];
        }
    } else {
        // ---- backward init at t=L-1: b = exp(end) ----
        const float b0 = endt[c * K_SZ + tid] * L2E;
        if (tid == 0) psh[0][0] = b0;
        __syncthreads();
        const float m0 = psh[0][0];
        a  = ex2f(b0 - m0);
        M2 = m0;

        // depth-4 prefetch ring, slices L-1 .. L-4 (clamped at 0)
        float p0 = __ldcs(e0p + (size_t)max(L - 1, 0) * tstride + tid);
        float p1 = __ldcs(e0p + (size_t)max(L - 2, 0) * tstride + tid);
        float p2 = __ldcs(e0p + (size_t)max(L - 3, 0) * tstride + tid);
        float p3 = __ldcs(e0p + (size_t)max(L - 4, 0) * tstride + tid);

        int t = L - 1;
        while (t > mid) {
            STEP_B(p0, t, 1); if (--t <= mid) break;
            STEP_B(p1, t, 0); if (--t <= mid) break;
            STEP_B(p2, t, 1); if (--t <= mid) break;
            STEP_B(p3, t, 0); --t;
        }
    }

    // ===== publish the half-chain state =====
    g_vec[blk][tid] = a;
    if (tid == 0) g_m2[blk] = M2;
}

// Combine: Z = sum_k a_mid[k] * b_mid[k];  out = num - (M2f + M2b + log2 Z)*ln2
__global__ void __launch_bounds__(32)
crf_combine_kernel(float* __restrict__ out)
{
    const int chain = blockIdx.x;
    const int lane  = threadIdx.x;
    const unsigned FULL = 0xffffffffu;

    const float* af = g_vec[2 * chain];
    const float* ab = g_vec[2 * chain + 1];

    float s = af[lane] * ab[lane] + af[lane + 32] * ab[lane + 32];
    #pragma unroll
    for (int off = 16; off; off >>= 1)
        s += __shfl_xor_sync(FULL, s, off);

    if (lane == 0) {
        const float den = (g_m2[2 * chain] + g_m2[2 * chain + 1] + lg2f(s)) * LN2;
        out[chain] = g_num[chain] - den;
    }
}

extern "C" void kernel_launch(void* const* d_in, const int* in_sizes, int n_in,
                              void* d_out, int out_size) {
    const float* emis   = (const float*)d_in[0];
    const int*   tags   = (const int*)  d_in[1];
    const int*   tok    = (const int*)  d_in[2];
    const float* trans  = (const float*)d_in[3];
    const float* startt = (const float*)d_in[4];
    const float* endt   = (const float*)d_in[5];
    float* out = (float*)d_out;

    crf_half_kernel<<<2 * N_CHAIN, 64>>>(emis, tags, tok, trans, startt, endt);
    crf_combine_kernel<<<N_CHAIN, 32>>>(out);
}

// round 12
// speedup vs baseline: 1.1174x; 1.0154x over previous
#include <cuda_runtime.h>
#include <cstdint>

// Problem constants (fixed shapes)
#define T_LEN 512
#define B_SZ  256
#define C_SZ  4
#define K_SZ  64
#define L2E   1.4426950408889634f
#define LN2   0.6931471805599453f

#define N_CHAIN (B_SZ * C_SZ)        // 1024

// Scratch for the forward/backward meet (allocation-free rule: device globals)
__device__ float g_vec[2 * N_CHAIN][K_SZ];   // [2*chain + dir][state]
__device__ float g_m2 [2 * N_CHAIN];         // log2 offsets
__device__ float g_num[N_CHAIN];             // finished numerators

// ---------- small PTX helpers ----------
static __device__ __forceinline__ float ex2f(float x) {
    float y; asm("ex2.approx.ftz.f32 %0, %1;" : "=f"(y) : "f"(x)); return y;
}
static __device__ __forceinline__ float lg2f(float x) {
    float y; asm("lg2.approx.f32 %0, %1;" : "=f"(y) : "f"(x)); return y;
}
static __device__ __forceinline__ unsigned long long pk2(float lo, float hi) {
    unsigned long long r;
    asm("mov.b64 %0, {%1, %2};" : "=l"(r) : "f"(lo), "f"(hi));
    return r;
}
static __device__ __forceinline__ void upk2(unsigned long long v, float& lo, float& hi) {
    asm("mov.b64 {%0, %1}, %2;" : "=f"(lo), "=f"(hi) : "l"(v));
}
// packed dual-FP32 FMA (Blackwell f32x2 pipe)
static __device__ __forceinline__ void fma2(unsigned long long& d,
                                            unsigned long long a,
                                            unsigned long long b) {
    asm("fma.rn.f32x2 %0, %1, %2, %0;" : "+l"(d) : "l"(a), "l"(b));
}
static __device__ __forceinline__ unsigned long long add2(unsigned long long a,
                                                          unsigned long long b) {
    unsigned long long d;
    asm("add.rn.f32x2 %0, %1, %2;" : "=l"(d) : "l"(a), "l"(b));
    return d;
}
// exact power-of-two renormalizer from fp32 exponent field (validated R7/R9)
static __device__ __forceinline__ void renorm(float v, float& r, float& ee) {
    const unsigned nb = __float_as_uint(v);
    const int ef = (int)(nb >> 23);
    ee = (float)(ef - 127);
    r  = __uint_as_float((unsigned)(254 - ef) << 23);   // 2^-(ef-127)
}

// Dual 64-wide dot product: lane owns two output slots (EA-, EB-sets of 32
// packed F pairs). Reads the broadcast 256B vector once (16 LDS.128).
// ALL internals underscore-prefixed: R10's NaN was caller-local `sA/sB`
// being shadowed by same-named macro internals, leaving the outputs
// uninitialized. Never reuse caller-visible names inside this macro.
#define MATVEC2(BUF, SUMA, SUMB, NORMV)                                        \
    do {                                                                       \
        const ulonglong2* _pd = reinterpret_cast<const ulonglong2*>(BUF);      \
        unsigned long long _aA0 = 0ull, _aA1 = 0ull, _aB0 = 0ull, _aB1 = 0ull; \
        _Pragma("unroll")                                                      \
        for (int _i = 0; _i < 16; _i++) {                                      \
            ulonglong2 _q = _pd[_i];                                           \
            if (_i == 0) { float _lo, _hi; upk2(_q.x, _lo, _hi); (NORMV) = _lo; } \
            fma2(_aA0, _q.x, EA[2 * _i]);                                      \
            fma2(_aB0, _q.x, EB[2 * _i]);                                      \
            fma2(_aA1, _q.y, EA[2 * _i + 1]);                                  \
            fma2(_aB1, _q.y, EB[2 * _i + 1]);                                  \
        }                                                                      \
        unsigned long long _s2A = add2(_aA0, _aA1);                            \
        unsigned long long _s2B = add2(_aB0, _aB1);                            \
        float _al, _ah, _bl, _bh;                                              \
        upk2(_s2A, _al, _ah);                                                  \
        upk2(_s2B, _bl, _bh);                                                  \
        (SUMA) = _al + _ah;                                                    \
        (SUMB) = _bl + _bh;                                                    \
    } while (0)

// Forward step: emission applied AFTER the matvec.
#define STEP_F(EV0, EV1, TT, P)                                                \
    do {                                                                       \
        const float _Et0 = ex2f((EV0) * L2E);                                  \
        const float _Et1 = ex2f((EV1) * L2E);                                  \
        {   const int _tn = min((TT) + 4, T_LEN - 1);                          \
            const float* _pp = e0p + (size_t)_tn * tstride;                    \
            (EV0) = __ldcs(_pp + lane);                                        \
            (EV1) = __ldcs(_pp + lane + 32); }                                 \
        psh[P][lane]      = a0;                                                \
        psh[P][lane + 32] = a1;                                                \
        __syncwarp();                                                          \
        float _sumA, _sumB, _nrm;                                              \
        MATVEC2(&psh[P][0], _sumA, _sumB, _nrm);                               \
        float _r, _ee;                                                         \
        renorm(_nrm, _r, _ee);                                                 \
        a0 = _sumA * (_Et0 * _r);                                              \
        a1 = _sumB * (_Et1 * _r);                                              \
        M2 += _ee;                                                             \
    } while (0)

// Backward step: emission folded BEFORE the matvec (b' = F (E_t ∘ b)).
#define STEP_B(EV0, EV1, TT, P)                                                \
    do {                                                                       \
        const float _c0 = a0 * ex2f((EV0) * L2E);                              \
        const float _c1 = a1 * ex2f((EV1) * L2E);                              \
        {   const int _tn = max((TT) - 4, 0);                                  \
            const float* _pp = e0p + (size_t)_tn * tstride;                    \
            (EV0) = __ldcs(_pp + lane);                                        \
            (EV1) = __ldcs(_pp + lane + 32); }                                 \
        psh[P][lane]      = _c0;                                               \
        psh[P][lane + 32] = _c1;                                               \
        __syncwarp();                                                          \
        float _sumA, _sumB, _nrm;                                              \
        MATVEC2(&psh[P][0], _sumA, _sumB, _nrm);                               \
        float _r, _ee;                                                         \
        renorm(_nrm, _r, _ee);                                                 \
        a0 = _sumA * _r;                                                       \
        a1 = _sumB * _r;                                                       \
        M2 += _ee;                                                             \
    } while (0)

// One half-chain per 32-thread block (one warp). blk = 2*chain + dir.
//   dir 0: forward,  steps t = 1..mid,   also computes the numerator.
//   dir 1: backward, steps t = L-1..mid+1.
// Lane owns states lane and lane+32.
__global__ void __launch_bounds__(32)
crf_half_kernel(const float* __restrict__ emis,    // (T,B,C,K)
                const int*   __restrict__ tags,    // (T,B,C)
                const int*   __restrict__ tok,     // (B,)
                const float* __restrict__ trans,   // (C,K,K)
                const float* __restrict__ startt,  // (C,K)
                const float* __restrict__ endt)    // (C,K)
{
    __shared__ __align__(16) float psh[2][K_SZ];

    const int blk   = blockIdx.x;
    const int dir   = blk & 1;
    const int chain = blk >> 1;
    const int b = chain >> 2;
    const int c = chain & 3;
    const int lane = threadIdx.x;
    const unsigned FULL = 0xffffffffu;

    int L = tok[b];
    L = min(max(L, 1), T_LEN);
    const int mid = (L - 1) >> 1;

    const float* e0p = emis + ((size_t)b * C_SZ + c) * K_SZ;   // t=0 slice
    const size_t tstride = (size_t)B_SZ * C_SZ * K_SZ;
    const float* tr = trans + c * K_SZ * K_SZ;

    // ===== numerator (forward blocks only) =====
    float nacc = 0.f;
    if (dir == 0) {
        for (int t = 1 + lane; t < L; t += 32) {
            int tp = tags[((t - 1) * B_SZ + b) * C_SZ + c];
            int tc = tags[(t * B_SZ + b) * C_SZ + c];
            nacc += trans[(c * K_SZ + tp) * K_SZ + tc]
                  + emis[(((size_t)t * B_SZ + b) * C_SZ + c) * K_SZ + tc];
        }
    }

    // ===== F registers =====
    // forward:  lane owns OUT states lane, lane+32 -> columns lane / lane+32
    //           packed over kp pairs: EA[j] = (F[2j][lane],   F[2j+1][lane])
    // backward: lane owns states lane, lane+32     -> rows lane / lane+32
    //           packed along kn:      EA[j] = (F[lane][2j],   F[lane][2j+1])
    unsigned long long EA[32], EB[32];
    if (dir == 0) {
        #pragma unroll
        for (int j = 0; j < 32; j++) {
            EA[j] = pk2(__expf(tr[(2 * j)     * K_SZ + lane]),
                        __expf(tr[(2 * j + 1) * K_SZ + lane]));
            EB[j] = pk2(__expf(tr[(2 * j)     * K_SZ + lane + 32]),
                        __expf(tr[(2 * j + 1) * K_SZ + lane + 32]));
        }
    } else {
        #pragma unroll
        for (int j = 0; j < 32; j++) {
            EA[j] = pk2(__expf(tr[lane * K_SZ + 2 * j]),
                        __expf(tr[lane * K_SZ + 2 * j + 1]));
            EB[j] = pk2(__expf(tr[(lane + 32) * K_SZ + 2 * j]),
                        __expf(tr[(lane + 32) * K_SZ + 2 * j + 1]));
        }
    }

    float a0, a1, M2;

    if (dir == 0) {
        // ---- forward init at t=0 ----
        const float i0 = (startt[c * K_SZ + lane]      + e0p[lane])      * L2E;
        const float i1 = (startt[c * K_SZ + lane + 32] + e0p[lane + 32]) * L2E;
        const float m0 = __shfl_sync(FULL, i0, 0);
        a0 = ex2f(i0 - m0);
        a1 = ex2f(i1 - m0);
        M2 = m0;

        // depth-4 prefetch ring, slices 1..4 (always in-bounds)
        float pA0 = __ldcs(e0p + 1 * tstride + lane);
        float pB0 = __ldcs(e0p + 1 * tstride + lane + 32);
        float pA1 = __ldcs(e0p + 2 * tstride + lane);
        float pB1 = __ldcs(e0p + 2 * tstride + lane + 32);
        float pA2 = __ldcs(e0p + 3 * tstride + lane);
        float pB2 = __ldcs(e0p + 3 * tstride + lane + 32);
        float pA3 = __ldcs(e0p + 4 * tstride + lane);
        float pB3 = __ldcs(e0p + 4 * tstride + lane + 32);

        int t = 1;
        while (t <= mid) {
            STEP_F(pA0, pB0, t, 1); if (++t > mid) break;
            STEP_F(pA1, pB1, t, 0); if (++t > mid) break;
            STEP_F(pA2, pB2, t, 1); if (++t > mid) break;
            STEP_F(pA3, pB3, t, 0); ++t;
        }

        // finish the numerator
        #pragma unroll
        for (int off = 16; off; off >>= 1)
            nacc += __shfl_xor_sync(FULL, nacc, off);
        if (lane == 0) {
            const int tag0 = tags[b * C_SZ + c];
            const int tagL = tags[((L - 1) * B_SZ + b) * C_SZ + c];
            g_num[chain] = nacc
                         + startt[c * K_SZ + tag0]
                         + e0p[tag0]
                         + endt[c * K_SZ + tagL];
        }
    } else {
        // ---- backward init at t=L-1: b = exp(end) ----
        const float i0 = endt[c * K_SZ + lane]      * L2E;
        const float i1 = endt[c * K_SZ + lane + 32] * L2E;
        const float m0 = __shfl_sync(FULL, i0, 0);
        a0 = ex2f(i0 - m0);
        a1 = ex2f(i1 - m0);
        M2 = m0;

        // depth-4 prefetch ring, slices L-1 .. L-4 (clamped at 0)
        const float* q1 = e0p + (size_t)max(L - 1, 0) * tstride;
        const float* q2 = e0p + (size_t)max(L - 2, 0) * tstride;
        const float* q3 = e0p + (size_t)max(L - 3, 0) * tstride;
        const float* q4 = e0p + (size_t)max(L - 4, 0) * tstride;
        float pA0 = __ldcs(q1 + lane), pB0 = __ldcs(q1 + lane + 32);
        float pA1 = __ldcs(q2 + lane), pB1 = __ldcs(q2 + lane + 32);
        float pA2 = __ldcs(q3 + lane), pB2 = __ldcs(q3 + lane + 32);
        float pA3 = __ldcs(q4 + lane), pB3 = __ldcs(q4 + lane + 32);

        int t = L - 1;
        while (t > mid) {
            STEP_B(pA0, pB0, t, 1); if (--t <= mid) break;
            STEP_B(pA1, pB1, t, 0); if (--t <= mid) break;
            STEP_B(pA2, pB2, t, 1); if (--t <= mid) break;
            STEP_B(pA3, pB3, t, 0); --t;
        }
    }

    // ===== publish the half-chain state =====
    g_vec[blk][lane]      = a0;
    g_vec[blk][lane + 32] = a1;
    if (lane == 0) g_m2[blk] = M2;
}

// Combine: Z = sum_k a_mid[k] * b_mid[k];  out = num - (M2f + M2b + log2 Z)*ln2
__global__ void __launch_bounds__(32)
crf_combine_kernel(float* __restrict__ out)
{
    const int chain = blockIdx.x;
    const int lane  = threadIdx.x;
    const unsigned FULL = 0xffffffffu;

    const float* af = g_vec[2 * chain];
    const float* ab = g_vec[2 * chain + 1];

    float s = af[lane] * ab[lane] + af[lane + 32] * ab[lane + 32];
    #pragma unroll
    for (int off = 16; off; off >>= 1)
        s += __shfl_xor_sync(FULL, s, off);

    if (lane == 0) {
        const float den = (g_m2[2 * chain] + g_m2[2 * chain + 1] + lg2f(s)) * LN2;
        out[chain] = g_num[chain] - den;
    }
}

extern "C" void kernel_launch(void* const* d_in, const int* in_sizes, int n_in,
                              void* d_out, int out_size) {
    const float* emis   = (const float*)d_in[0];
    const int*   tags   = (const int*)  d_in[1];
    const int*   tok    = (const int*)  d_in[2];
    const float* trans  = (const float*)d_in[3];
    const float* startt = (const float*)d_in[4];
    const float* endt   = (const float*)d_in[5];
    float* out = (float*)d_out;

    crf_half_kernel<<<2 * N_CHAIN, 32>>>(emis, tags, tok, trans, startt, endt);
    crf_combine_kernel<<<N_CHAIN, 32>>>(out);
}

// round 13
// speedup vs baseline: 1.1611x; 1.0391x over previous
#include <cuda_runtime.h>
#include <cstdint>

// Problem constants (fixed shapes)
#define T_LEN 512
#define B_SZ  256
#define C_SZ  4
#define K_SZ  64
#define L2E   1.4426950408889634f
#define LN2   0.6931471805599453f

#define N_CHAIN (B_SZ * C_SZ)        // 1024
#define TSTR2   ((B_SZ * C_SZ * K_SZ) / 2)   // time stride in float2 units

// Scratch for the forward/backward meet (allocation-free rule: device globals)
__device__ float g_vec[2 * N_CHAIN][K_SZ];   // [2*chain + dir][state]
__device__ float g_m2 [2 * N_CHAIN];         // log2 offsets
__device__ float g_num[N_CHAIN];             // finished numerators

// ---------- small PTX helpers ----------
static __device__ __forceinline__ float ex2f(float x) {
    float y; asm("ex2.approx.ftz.f32 %0, %1;" : "=f"(y) : "f"(x)); return y;
}
static __device__ __forceinline__ float lg2f(float x) {
    float y; asm("lg2.approx.f32 %0, %1;" : "=f"(y) : "f"(x)); return y;
}
static __device__ __forceinline__ unsigned long long pk2(float lo, float hi) {
    unsigned long long r;
    asm("mov.b64 %0, {%1, %2};" : "=l"(r) : "f"(lo), "f"(hi));
    return r;
}
static __device__ __forceinline__ void upk2(unsigned long long v, float& lo, float& hi) {
    asm("mov.b64 {%0, %1}, %2;" : "=f"(lo), "=f"(hi) : "l"(v));
}
// packed dual-FP32 FMA (Blackwell f32x2 pipe)
static __device__ __forceinline__ void fma2(unsigned long long& d,
                                            unsigned long long a,
                                            unsigned long long b) {
    asm("fma.rn.f32x2 %0, %1, %2, %0;" : "+l"(d) : "l"(a), "l"(b));
}
static __device__ __forceinline__ unsigned long long add2(unsigned long long a,
                                                          unsigned long long b) {
    unsigned long long d;
    asm("add.rn.f32x2 %0, %1, %2;" : "=l"(d) : "l"(a), "l"(b));
    return d;
}

// Dual 64-wide dot product (macro-hygiene: all internals underscore-prefixed;
// R10's NaN came from shadowing caller locals). Reads the broadcast 256B
// vector once (16 LDS.128); extracts state-0 value for the renormalizer.
#define MATVEC2(BUF, SUMA, SUMB, NORMV)                                        \
    do {                                                                       \
        const ulonglong2* _pd = reinterpret_cast<const ulonglong2*>(BUF);      \
        unsigned long long _aA0 = 0ull, _aA1 = 0ull, _aB0 = 0ull, _aB1 = 0ull; \
        _Pragma("unroll")                                                      \
        for (int _i = 0; _i < 16; _i++) {                                      \
            ulonglong2 _q = _pd[_i];                                           \
            if (_i == 0) { float _lo, _hi; upk2(_q.x, _lo, _hi); (NORMV) = _lo; } \
            fma2(_aA0, _q.x, EA[2 * _i]);                                      \
            fma2(_aB0, _q.x, EB[2 * _i]);                                      \
            fma2(_aA1, _q.y, EA[2 * _i + 1]);                                  \
            fma2(_aB1, _q.y, EB[2 * _i + 1]);                                  \
        }                                                                      \
        unsigned long long _s2A = add2(_aA0, _aA1);                            \
        unsigned long long _s2B = add2(_aB0, _aB1);                            \
        float _al, _ah, _bl, _bh;                                              \
        upk2(_s2A, _al, _ah);                                                  \
        upk2(_s2B, _bl, _bh);                                                  \
        (SUMA) = _al + _ah;                                                    \
        (SUMB) = _bl + _bh;                                                    \
    } while (0)

// Shared step tail: renorm by exact power-of-two from state-0's exponent
// field, accumulate the (biased) exponent as an integer.
#define RENORM_I(NRM, RV)                                                      \
    const unsigned _nb = __float_as_uint(NRM);                                 \
    const int _ef = (int)(_nb >> 23);                                          \
    const float RV = __uint_as_float((unsigned)(254 - _ef) << 23);             \
    M2i += _ef;

// Forward step: emission applied AFTER the matvec. PE = float2 prefetch slot
// (emissions for states 2l, 2l+1). Rolling pointer, no clamp needed
// (max prefetch slice = mid + 4 <= 259 < T_LEN).
#define STEP_F(PE, P)                                                          \
    do {                                                                       \
        const float _Et0 = ex2f((PE).x * L2E);                                 \
        const float _Et1 = ex2f((PE).y * L2E);                                 \
        (PE) = __ldcs(prefp);                                                  \
        prefp += TSTR2;                                                        \
        *reinterpret_cast<float2*>(&psh[P][2 * lane]) = make_float2(a0, a1);   \
        __syncwarp();                                                          \
        float _sumA, _sumB, _nrm;                                              \
        MATVEC2(&psh[P][0], _sumA, _sumB, _nrm);                               \
        RENORM_I(_nrm, _r);                                                    \
        a0 = _sumA * (_Et0 * _r);                                              \
        a1 = _sumB * (_Et1 * _r);                                              \
    } while (0)

// Backward step: emission folded BEFORE the matvec. Rolling pointer clamped
// at the t=0 slice (prefetched values past the end are never consumed).
#define STEP_B(PE, P)                                                          \
    do {                                                                       \
        const float _c0 = a0 * ex2f((PE).x * L2E);                             \
        const float _c1 = a1 * ex2f((PE).y * L2E);                             \
        (PE) = __ldcs(prefp);                                                  \
        prefp = (prefp > pbase) ? (prefp - TSTR2) : pbase;                     \
        *reinterpret_cast<float2*>(&psh[P][2 * lane]) = make_float2(_c0, _c1); \
        __syncwarp();                                                          \
        float _sumA, _sumB, _nrm;                                              \
        MATVEC2(&psh[P][0], _sumA, _sumB, _nrm);                               \
        RENORM_I(_nrm, _r);                                                    \
        a0 = _sumA * _r;                                                       \
        a1 = _sumB * _r;                                                       \
    } while (0)

#define RUN_STEPS(STEP)                                                        \
    do {                                                                       \
        int _nq = nsteps >> 2;                                                 \
        const int _nr = nsteps & 3;                                            \
        while (_nq--) { STEP(p0, 1); STEP(p1, 0); STEP(p2, 1); STEP(p3, 0); }  \
        if (_nr) {                                                             \
            STEP(p0, 1);                                                       \
            if (_nr > 1) {                                                     \
                STEP(p1, 0);                                                   \
                if (_nr > 2) STEP(p2, 1);                                      \
            }                                                                  \
        }                                                                      \
    } while (0)

// One half-chain per 32-thread block (one warp). blk = 2*chain + dir.
//   dir 0: forward,  steps t = 1..mid,   also computes the numerator.
//   dir 1: backward, steps t = L-1..mid+1.
// Lane owns ADJACENT states 2*lane and 2*lane+1 (vector LDG.64/STS.64).
__global__ void __launch_bounds__(32)
crf_half_kernel(const float* __restrict__ emis,    // (T,B,C,K)
                const int*   __restrict__ tags,    // (T,B,C)
                const int*   __restrict__ tok,     // (B,)
                const float* __restrict__ trans,   // (C,K,K)
                const float* __restrict__ startt,  // (C,K)
                const float* __restrict__ endt)    // (C,K)
{
    __shared__ __align__(16) float psh[2][K_SZ];

    const int blk   = blockIdx.x;
    const int dir   = blk & 1;
    const int chain = blk >> 1;
    const int b = chain >> 2;
    const int c = chain & 3;
    const int lane = threadIdx.x;
    const int s0 = 2 * lane;             // first owned state
    const unsigned FULL = 0xffffffffu;

    int L = tok[b];
    L = min(max(L, 1), T_LEN);
    const int mid = (L - 1) >> 1;

    const float* e0p = emis + ((size_t)b * C_SZ + c) * K_SZ;   // t=0 slice
    const float2* pbase = reinterpret_cast<const float2*>(e0p) + lane;
    const float* tr = trans + c * K_SZ * K_SZ;

    // ===== numerator (forward blocks only) =====
    float nacc = 0.f;
    if (dir == 0) {
        for (int t = 1 + lane; t < L; t += 32) {
            int tp = tags[((t - 1) * B_SZ + b) * C_SZ + c];
            int tc = tags[(t * B_SZ + b) * C_SZ + c];
            nacc += trans[(c * K_SZ + tp) * K_SZ + tc]
                  + emis[(((size_t)t * B_SZ + b) * C_SZ + c) * K_SZ + tc];
        }
    }

    // ===== F registers =====
    // forward:  lane owns OUT states s0, s0+1 -> columns s0 / s0+1
    //           EA[j] = (F[2j][s0], F[2j+1][s0]);  EB: column s0+1
    // backward: lane owns states s0, s0+1     -> rows s0 / s0+1
    //           EA[j] = (F[s0][2j], F[s0][2j+1]);  EB: row s0+1
    unsigned long long EA[32], EB[32];
    if (dir == 0) {
        #pragma unroll
        for (int j = 0; j < 32; j++) {
            EA[j] = pk2(__expf(tr[(2 * j)     * K_SZ + s0]),
                        __expf(tr[(2 * j + 1) * K_SZ + s0]));
            EB[j] = pk2(__expf(tr[(2 * j)     * K_SZ + s0 + 1]),
                        __expf(tr[(2 * j + 1) * K_SZ + s0 + 1]));
        }
    } else {
        #pragma unroll
        for (int j = 0; j < 32; j++) {
            EA[j] = pk2(__expf(tr[s0 * K_SZ + 2 * j]),
                        __expf(tr[s0 * K_SZ + 2 * j + 1]));
            EB[j] = pk2(__expf(tr[(s0 + 1) * K_SZ + 2 * j]),
                        __expf(tr[(s0 + 1) * K_SZ + 2 * j + 1]));
        }
    }

    float a0, a1, m0;
    int M2i = 0;                       // biased exponent accumulator
    int nsteps;

    if (dir == 0) {
        nsteps = mid;

        // ---- forward init at t=0 ----
        const float2 e0v = pbase[0];
        const float2 st  = *reinterpret_cast<const float2*>(&startt[c * K_SZ + s0]);
        const float i0 = (st.x + e0v.x) * L2E;
        const float i1 = (st.y + e0v.y) * L2E;
        m0 = __shfl_sync(FULL, i0, 0);
        a0 = ex2f(i0 - m0);
        a1 = ex2f(i1 - m0);

        // prefill depth-4 ring (slices 1..4, always in-bounds)
        float2 p0 = __ldcs(pbase + 1 * TSTR2);
        float2 p1 = __ldcs(pbase + 2 * TSTR2);
        float2 p2 = __ldcs(pbase + 3 * TSTR2);
        float2 p3 = __ldcs(pbase + 4 * TSTR2);
        const float2* prefp = pbase + 5 * TSTR2;   // next prefetch slice

        RUN_STEPS(STEP_F);

        // finish the numerator
        #pragma unroll
        for (int off = 16; off; off >>= 1)
            nacc += __shfl_xor_sync(FULL, nacc, off);
        if (lane == 0) {
            const int tag0 = tags[b * C_SZ + c];
            const int tagL = tags[((L - 1) * B_SZ + b) * C_SZ + c];
            g_num[chain] = nacc
                         + startt[c * K_SZ + tag0]
                         + e0p[tag0]
                         + endt[c * K_SZ + tagL];
        }
    } else {
        nsteps = L - 1 - mid;

        // ---- backward init at t=L-1: b = exp(end) ----
        const float2 en = *reinterpret_cast<const float2*>(&endt[c * K_SZ + s0]);
        const float i0 = en.x * L2E;
        const float i1 = en.y * L2E;
        m0 = __shfl_sync(FULL, i0, 0);
        a0 = ex2f(i0 - m0);
        a1 = ex2f(i1 - m0);

        // prefill depth-4 ring (slices L-1 .. L-4, clamped at 0)
        float2 p0 = __ldcs(pbase + (size_t)max(L - 1, 0) * TSTR2);
        float2 p1 = __ldcs(pbase + (size_t)max(L - 2, 0) * TSTR2);
        float2 p2 = __ldcs(pbase + (size_t)max(L - 3, 0) * TSTR2);
        float2 p3 = __ldcs(pbase + (size_t)max(L - 4, 0) * TSTR2);
        const float2* prefp = pbase + (size_t)max(L - 5, 0) * TSTR2;

        RUN_STEPS(STEP_B);
    }

    // ===== publish the half-chain state =====
    reinterpret_cast<float2*>(&g_vec[blk][s0])[0] = make_float2(a0, a1);
    if (lane == 0)
        g_m2[blk] = m0 + (float)(M2i - 127 * nsteps);
}

// Combine: Z = sum_k a_mid[k] * b_mid[k];  out = num - (M2f + M2b + log2 Z)*ln2
__global__ void __launch_bounds__(32)
crf_combine_kernel(float* __restrict__ out)
{
    const int chain = blockIdx.x;
    const int lane  = threadIdx.x;
    const unsigned FULL = 0xffffffffu;

    const float* af = g_vec[2 * chain];
    const float* ab = g_vec[2 * chain + 1];

    float s = af[lane] * ab[lane] + af[lane + 32] * ab[lane + 32];
    #pragma unroll
    for (int off = 16; off; off >>= 1)
        s += __shfl_xor_sync(FULL, s, off);

    if (lane == 0) {
        const float den = (g_m2[2 * chain] + g_m2[2 * chain + 1] + lg2f(s)) * LN2;
        out[chain] = g_num[chain] - den;
    }
}

extern "C" void kernel_launch(void* const* d_in, const int* in_sizes, int n_in,
                              void* d_out, int out_size) {
    const float* emis   = (const float*)d_in[0];
    const int*   tags   = (const int*)  d_in[1];
    const int*   tok    = (const int*)  d_in[2];
    const float* trans  = (const float*)d_in[3];
    const float* startt = (const float*)d_in[4];
    const float* endt   = (const float*)d_in[5];
    float* out = (float*)d_out;

    crf_half_kernel<<<2 * N_CHAIN, 32>>>(emis, tags, tok, trans, startt, endt);
    crf_combine_kernel<<<N_CHAIN, 32>>>(out);
}